// round 13
// baseline (speedup 1.0000x reference)
#include <cuda_runtime.h>
#include <math.h>

#define B_ 128
#define N_ 512
#define U_ 128
#define MSTEPS 70

// ---------------- device scratch ----------------
__device__ float g_kv [B_*128*N_];     // [b][h*16+d][n]
__device__ float g_vv [B_*128*N_];     // [b][h*16+d][n]
__device__ float g_kvf[B_*U_*N_];      // [b][u][n]
__device__ float g_gum[MSTEPS*65536];  // gumbel noise [t][b*512+n]
__device__ float g_WTkvf[U_*U_];
__device__ float g_WTqvf[U_*U_];
__device__ float g_qvpT[128*384];      // qv_p transposed: [h*16+d][x]
__device__ int   g_route[(MSTEPS+1)*B_];
__device__ float g_flp[B_];
__device__ float g_len[B_];
__device__ int   g_doneA[2];
__device__ unsigned g_matched[B_];
__device__ int   g_check[B_];
__device__ int   g_targetA[2][B_];
__device__ float g_logprob[B_];
__device__ unsigned g_keys[MSTEPS*2];
__device__ int   g_cnt;                // grid barrier counter
__device__ int   g_gen;                // grid barrier generation

// ---------------- Threefry-2x32-20 (JAX partitionable) ----------------
__device__ __forceinline__ void tf2x32(unsigned k0, unsigned k1, unsigned &x0, unsigned &x1) {
    unsigned ks2 = k0 ^ k1 ^ 0x1BD11BDAu;
    x0 += k0; x1 += k1;
#define TFR(r) { x0 += x1; x1 = (x1<<(r)) | (x1>>(32-(r))); x1 ^= x0; }
    TFR(13) TFR(15) TFR(26) TFR(6)
    x0 += k1;  x1 += ks2 + 1u;
    TFR(17) TFR(29) TFR(16) TFR(24)
    x0 += ks2; x1 += k0 + 2u;
    TFR(13) TFR(15) TFR(26) TFR(6)
    x0 += k0;  x1 += k1 + 3u;
    TFR(17) TFR(29) TFR(16) TFR(24)
    x0 += k1;  x1 += ks2 + 4u;
    TFR(13) TFR(15) TFR(26) TFR(6)
    x0 += ks2; x1 += k0 + 5u;
#undef TFR
}

// ---------------- accurate f32 transcendentals ----------------
__device__ __forceinline__ float expf_acc(float x) {
    if (x < -87.0f) return 0.f;
    float k = rintf(x * 1.4426950408889634f);
    float r = fmaf(k, -0.693359375f, x);
    r = fmaf(k, 2.12194440e-4f, r);
    float z = r * r;
    float p = 1.9875691500e-4f;
    p = fmaf(p, r, 1.3981999507e-3f);
    p = fmaf(p, r, 8.3334519073e-3f);
    p = fmaf(p, r, 4.1665795894e-2f);
    p = fmaf(p, r, 1.6666665459e-1f);
    p = fmaf(p, r, 5.0000001201e-1f);
    float res = fmaf(z, p, r) + 1.0f;
    int ki = (int)k;
    return res * __int_as_float((ki + 127) << 23);
}

__device__ __forceinline__ float logf_acc(float x) {
    int hx = __float_as_int(x);
    int k = ((hx >> 23) & 0xff) - 127;
    hx = (hx & 0x7fffff) | 0x3f800000;
    float m = __int_as_float(hx);
    if (m >= 1.41421356237f) { m *= 0.5f; k++; }
    float f = m - 1.0f;
    float s = __fdiv_rn(f, 2.0f + f);
    float z = s * s;
    float w = z * z;
    float t1 = w * fmaf(w, 0.24279078841f, 0.40000972152f);
    float t2 = z * fmaf(w, 0.28498786688f, 0.66666662693f);
    float R = t2 + t1;
    float hfsq = 0.5f * f * f;
    float dk = (float)k;
    float r = fmaf(s, hfsq + R, dk * 9.0580006145e-06f);
    return dk * 0.69313812256f - ((hfsq - r) - f);
}

// ---------------- XLA fast-tanh ----------------
__device__ __forceinline__ float xla_tanhf(float x) {
    float ax = fabsf(x);
    const float cl = 7.90531110763549805f;
    float xc = fminf(fmaxf(x, -cl), cl);
    float x2 = xc * xc;
    float p = fmaf(x2, -2.76076847742355e-16f, 2.00018790482477e-13f);
    p = fmaf(x2, p, -8.60467152213735e-11f);
    p = fmaf(x2, p,  5.12229709037114e-08f);
    p = fmaf(x2, p,  1.48572235717979e-05f);
    p = fmaf(x2, p,  6.37261928875436e-04f);
    p = fmaf(x2, p,  4.89352455891786e-03f);
    p = p * xc;
    float q = fmaf(x2, 1.19825839466702e-06f, 1.18534705686654e-04f);
    q = fmaf(x2, q, 2.26843463243900e-03f);
    q = fmaf(x2, q, 4.89352518554385e-03f);
    float r = __fdiv_rn(p, q);
    return (ax < 0.0004f) ? x : r;
}

// ---------------- L2 policy loads ----------------
__device__ __forceinline__ unsigned long long pol_evict_last() {
    unsigned long long p;
    asm("createpolicy.fractional.L2::evict_last.b64 %0, 1.0;" : "=l"(p));
    return p;
}
__device__ __forceinline__ unsigned long long pol_evict_first() {
    unsigned long long p;
    asm("createpolicy.fractional.L2::evict_first.b64 %0, 1.0;" : "=l"(p));
    return p;
}
__device__ __forceinline__ float ldg_hint(const float* p, unsigned long long pol) {
    float v;
    asm("ld.global.nc.L2::cache_hint.f32 %0,[%1],%2;" : "=f"(v) : "l"(p), "l"(pol));
    return v;
}

// ---------------- init ----------------
__global__ void k_init(const int* __restrict__ obj, const int* __restrict__ hml) {
    int b = threadIdx.x;
    for (int i = b; i < (MSTEPS+1)*B_; i += B_) g_route[i] = 0;
    g_flp[b] = 0.f; g_len[b] = 0.f;
    if (b == 0) { g_doneA[0] = 0; g_doneA[1] = 0; g_cnt = 0; g_gen = 0; }
    if (b < MSTEPS) {
        unsigned x0 = 0u, x1 = (unsigned)b;
        tf2x32(0u, 42u, x0, x1);
        g_keys[2*b] = x0; g_keys[2*b+1] = x1;
    }
    int lz = 0;
    for (int m = 0; m < 16; m++) lz |= (hml[b*16 + m] == 0);
    int hz = __syncthreads_or(lz);
    unsigned mk = 0;
    for (int m = 0; m < 16; m++) {
        int v = hml[b*16 + m]; int mt = 0;
        for (int k = 0; k < 4; k++) mt |= (obj[k] == v);
        if (mt) mk |= (1u << m);
    }
    if (hz) mk |= 1u;
    g_matched[b] = mk;
    g_check[b] = (mk == 0xFFFFu) ? 1 : 0;
}

// ---------------- transposes (runs once) ----------------
__global__ void k_tw(const float* __restrict__ kvfW, const float* __restrict__ qvfW,
                     const float* __restrict__ qv_p) {
    int i = blockIdx.x * 256 + threadIdx.x;   // 49152 threads
    if (i < 16384) {
        int u = i >> 7, v = i & 127;
        g_WTkvf[v*128 + u] = kvfW[i];
        g_WTqvf[v*128 + u] = qvfW[i];
    }
    int r = i / 384, x = i % 384;
    g_qvpT[i] = qv_p[x*128 + r];
}

// ---------------- gumbel noise ----------------
__global__ void k_gum() {
    int idx = blockIdx.x * 512 + threadIdx.x;
    int t = idx >> 16, f = idx & 65535;
    unsigned x0 = 0u, x1 = (unsigned)f;
    tf2x32(g_keys[2*t], g_keys[2*t+1], x0, x1);
    unsigned bits = x0 ^ x1;
    float u0 = __uint_as_float((bits >> 9) | 0x3f800000u) - 1.0f;
    const float TINY = 1.17549435082228751e-38f;
    float uu = fmaxf(TINY, u0 + TINY);
    g_gum[idx] = -logf_acc(-logf_acc(uu));
}

// ---------------- precompute kv, vv (n-tile 16) ----------------
__global__ void k_prep_kv(const float* __restrict__ hvec, const float* __restrict__ kv_p,
                          const float* __restrict__ vv_p) {
    int b = blockIdx.y, n0 = blockIdx.x * 16;
    int t = threadIdx.x;
    __shared__ float hs[16*128];
    for (int i = t; i < 16*128; i += 128)
        hs[i] = hvec[(b*N_ + n0 + (i >> 7))*U_ + (i & 127)];
    __syncthreads();
    float ak[16], av[16];
#pragma unroll
    for (int j = 0; j < 16; j++) { ak[j] = 0.f; av[j] = 0.f; }
    for (int x = 0; x < 128; x++) {
        float kp = kv_p[x*128 + t];
        float vp = vv_p[x*128 + t];
#pragma unroll
        for (int j = 0; j < 16; j++) {
            float hx = hs[j*128 + x];
            ak[j] = fmaf(kp, hx, ak[j]);
            av[j] = fmaf(vp, hx, av[j]);
        }
    }
#pragma unroll
    for (int j = 0; j < 16; j++) {
        g_kv[(b*128 + t)*N_ + n0 + j] = ak[j];
        g_vv[(b*128 + t)*N_ + n0 + j] = av[j];
    }
}

// ---------------- precompute kvf (n-tile 16) ----------------
__global__ void k_prep_kvf(const float* __restrict__ hvec, const float* __restrict__ bias) {
    int b = blockIdx.y, n0 = blockIdx.x * 16;
    int u = threadIdx.x;
    __shared__ float hs[16*128];
    for (int i = u; i < 16*128; i += 128)
        hs[i] = hvec[(b*N_ + n0 + (i >> 7))*U_ + (i & 127)];
    __syncthreads();
    float a[16];
#pragma unroll
    for (int j = 0; j < 16; j++) a[j] = 0.f;
    for (int v = 0; v < 128; v++) {
        float w = g_WTkvf[v*128 + u];
#pragma unroll
        for (int j = 0; j < 16; j++) a[j] = fmaf(w, hs[j*128 + v], a[j]);
    }
    float bb = bias[u];
#pragma unroll
    for (int j = 0; j < 16; j++) g_kvf[(b*128 + u)*N_ + n0 + j] = a[j] + bb;
}

// ---------------- persistent multi-step kernel ----------------
__global__ void __launch_bounds__(1024, 1)
k_steps(const float* __restrict__ hvec, const float* __restrict__ hbar,
        const int* __restrict__ adj,
        const float* __restrict__ vec_1, const float* __restrict__ vec_f,
        const float* __restrict__ ov_p, const float* __restrict__ qvf_b,
        const int* __restrict__ obj, const int* __restrict__ hml) {
    int b = blockIdx.x;
    int tid = threadIdx.x;
    int half = tid >> 9;
    int hn   = tid & 511;
    int lane = tid & 31;
    int wid  = tid >> 5;
    int hwid = wid & 15;

    __shared__ float c_sh[384];
    __shared__ float qv_sh[128];
    __shared__ float w_sh[8][512];
    __shared__ float s_redM[2][16][4];
    __shared__ float s_mx[8], s_sum[8];
    __shared__ float rec_sh[128];
    __shared__ float hc_sh[128];
    __shared__ float qvf_sh[128];
    __shared__ float logits_sh[512];
    __shared__ float s_v[16]; __shared__ int s_i[16];
    __shared__ float s_m[16], s_s[16];
    __shared__ float s_gmx;
    __shared__ int s_last, s_check, s_done;
    __shared__ int s_t[128];

    unsigned long long PEL = pol_evict_last();
    unsigned long long PEF = pol_evict_first();

    bool broke = false;

    for (int t = 0; t < MSTEPS; t++) {
        // ---- phase 0: apply previous step's sampled targets (stats) ----
        if (t == 0) {
            if (tid == 0) { s_last = 0; s_check = g_check[b]; s_done = 0; }
        } else {
            if (tid < 128) s_t[tid] = g_targetA[(t-1) & 1][tid];
            __syncthreads();
            if (tid == 0) {
                int done_prev = g_doneA[(t-1) & 1];
                int a = 1;
                for (int i = 0; i < 128; i++) a &= (s_t[i] == 0);
                int done_t = (done_prev || a) ? 1 : 0;
                int tg = done_prev ? 0 : s_t[b];
                g_route[t*B_ + b] = tg;
                if (!done_t) {
                    g_flp[b] += g_logprob[b];
                    g_len[b] += (tg != 0) ? 1.f : 0.f;
                }
                unsigned mk = g_matched[b];
#pragma unroll
                for (int m = 0; m < 16; m++) {
                    int hv = hml[b*16 + m]; int mt = 0;
#pragma unroll
                    for (int k2 = 0; k2 < 4; k2++) mt |= (obj[tg*4 + k2] == hv);
                    if (mt) mk |= (1u << m);
                }
                g_matched[b] = mk;
                s_last = tg; s_check = (mk == 0xFFFFu) ? 1 : 0; s_done = done_t;
                if (b == 0) g_doneA[t & 1] = done_t;
            }
        }
        __syncthreads();
        if (s_done) { broke = true; break; }   // uniform across blocks

        // ---- context vector ----
        if (tid < 384) {
            float v;
            if (t == 0) {
                v = (tid < 128) ? hbar[tid]
                  : (tid < 256) ? vec_1[b*U_ + tid - 128]
                                : vec_f[b*U_ + tid - 256];
            } else {
                int previ  = g_route[(t-1)*B_ + b];
                int firsti = (t == 1) ? s_last : g_route[B_ + b];
                v = (tid < 128) ? hbar[tid]
                  : (tid < 256) ? hvec[(b*N_ + previ)*U_ + tid - 128]
                                : hvec[(b*N_ + firsti)*U_ + tid - 256];
            }
            c_sh[tid] = v;
        }
        __syncthreads();

        // ---- qv (coalesced transposed qv_p) ----
        {
            int d = hwid;
            for (int hh = 0; hh < 4; hh++) {
                int h = half*4 + hh;
                const float* qp = &g_qvpT[(h*16 + d)*384];
                float acc = 0.f;
                for (int x = lane; x < 384; x += 32)
                    acc = fmaf(qp[x], c_sh[x], acc);
                for (int o = 16; o > 0; o >>= 1) acc += __shfl_down_sync(0xffffffffu, acc, o);
                if (lane == 0) qv_sh[h*16 + d] = acc;
            }
        }
        __syncthreads();

        // ---- attention scores ----
        const int n = hn;
        const int adjv = adj[s_last*N_ + n];
        const bool adj_ok = adjv != 0;
        const bool dem_ok = (n == 0) ? (s_check != 0) : (s_check == 0);

        float m4[4], e4[4];
#pragma unroll
        for (int hh = 0; hh < 4; hh++) {
            int h = half*4 + hh;
            int base = (b*128 + h*16)*N_ + n;
            float acc = 0.f;
#pragma unroll
            for (int d = 0; d < 16; d++) acc = fmaf(qv_sh[h*16 + d], ldg_hint(&g_kv[base + d*N_], PEF), acc);
            m4[hh] = adj_ok ? (dem_ok ? acc*0.25f : -1e10f) : -1e30f;
        }
#pragma unroll
        for (int hh = 0; hh < 4; hh++) {
            float v = m4[hh];
            for (int o = 16; o > 0; o >>= 1) v = fmaxf(v, __shfl_down_sync(0xffffffffu, v, o));
            if (lane == 0) s_redM[half][hwid][hh] = v;
        }
        __syncthreads();
        if (tid < 8) {
            float x = s_redM[tid>>2][0][tid&3];
            for (int i = 1; i < 16; i++) x = fmaxf(x, s_redM[tid>>2][i][tid&3]);
            s_mx[tid] = x;
        }
        __syncthreads();
#pragma unroll
        for (int hh = 0; hh < 4; hh++) {
            float e = expf_acc(m4[hh] - s_mx[half*4 + hh]);
            e4[hh] = e;
            for (int o = 16; o > 0; o >>= 1) e += __shfl_down_sync(0xffffffffu, e, o);
            if (lane == 0) s_redM[half][hwid][hh] = e;
        }
        __syncthreads();
        if (tid < 8) {
            float x = 0.f;
            for (int i = 0; i < 16; i++) x += s_redM[tid>>2][i][tid&3];
            s_sum[tid] = x;
        }
        __syncthreads();
#pragma unroll
        for (int hh = 0; hh < 4; hh++)
            w_sh[half*4 + hh][n] = __fdiv_rn(e4[hh], s_sum[half*4 + hh]);
        __syncthreads();

        // ---- rec via warp-per-row ----
        {
            int r0 = wid * 4;
#pragma unroll
            for (int rr = 0; rr < 4; rr++) {
                int r = r0 + rr;
                int h = r >> 4;
                const float* vvp = &g_vv[(b*128 + r)*N_];
                float acc = 0.f;
#pragma unroll
                for (int k = 0; k < 16; k++) {
                    int nn = lane + k*32;
                    acc = fmaf(w_sh[h][nn], ldg_hint(&vvp[nn], PEL), acc);
                }
                for (int o = 16; o > 0; o >>= 1) acc += __shfl_down_sync(0xffffffffu, acc, o);
                if (lane == 0) rec_sh[r] = acc;
            }
        }
        __syncthreads();

        // ---- FC ----
        if (tid < 128) {
            float a = 0.f;
            for (int i = 0; i < 128; i++) a = fmaf(ov_p[i*128 + tid], rec_sh[i], a);
            hc_sh[tid] = a;
        }
        __syncthreads();
        if (tid < 128) {
            float a = 0.f;
            for (int v = 0; v < 128; v++) a = fmaf(g_WTqvf[v*128 + tid], hc_sh[v], a);
            qvf_sh[tid] = a + qvf_b[tid];
        }
        __syncthreads();

        // ---- logits + gumbel sample ----
        float lg = 0.f;
        if (tid < 512) {
            float acc = 0.f;
            int base = b*128*N_ + n;
            for (int u = 0; u < 128; u++) acc = fmaf(qvf_sh[u], ldg_hint(&g_kvf[base + u*N_], PEL), acc);
            const float SQRTU = 11.3137084989847603904f;
            float cf = 10.0f * xla_tanhf(__fdiv_rn(acc, SQRTU));
            lg = adj_ok ? (dem_ok ? cf : -1e10f) : -1e30f;
            logits_sh[n] = lg;
            float g1 = ldg_hint(&g_gum[t*65536 + b*512 + n], PEF);
            float val = lg + g1;

            float bv = val; int bi = n;
#pragma unroll
            for (int o = 16; o > 0; o >>= 1) {
                float ov = __shfl_down_sync(0xffffffffu, bv, o);
                int   oi = __shfl_down_sync(0xffffffffu, bi, o);
                if (ov > bv || (ov == bv && oi < bi)) { bv = ov; bi = oi; }
            }
            float mv = lg;
            for (int o = 16; o > 0; o >>= 1) mv = fmaxf(mv, __shfl_down_sync(0xffffffffu, mv, o));
            if (lane == 0) { s_v[wid] = bv; s_i[wid] = bi; s_m[wid] = mv; }
        }
        __syncthreads();
        if (tid == 0) { float x = s_m[0]; for (int i = 1; i < 16; i++) x = fmaxf(x, s_m[i]); s_gmx = x; }
        __syncthreads();
        if (tid < 512) {
            float ee = expf_acc(lg - s_gmx);
            for (int o = 16; o > 0; o >>= 1) ee += __shfl_down_sync(0xffffffffu, ee, o);
            if (lane == 0) s_s[wid] = ee;
        }
        __syncthreads();
        if (tid == 0) {
            float bbv = s_v[0]; int bbi = s_i[0];
            for (int i = 1; i < 16; i++) {
                if (s_v[i] > bbv || (s_v[i] == bbv && s_i[i] < bbi)) { bbv = s_v[i]; bbi = s_i[i]; }
            }
            float sum = 0.f;
            for (int i = 0; i < 16; i++) sum += s_s[i];
            g_targetA[t & 1][b] = bbi;
            g_logprob[b] = (logits_sh[bbi] - s_gmx) - logf_acc(sum);
        }

        // ---- device-wide barrier between steps ----
        __syncthreads();
        if (tid == 0) {
            __threadfence();
            int gen = *((volatile int*)&g_gen);
            int old = atomicAdd(&g_cnt, 1);
            if (old == B_ - 1) {
                g_cnt = 0;
                __threadfence();
                *((volatile int*)&g_gen) = gen + 1;
            } else {
                while (*((volatile int*)&g_gen) == gen) { }
            }
        }
        __syncthreads();
    }

    // if we broke early, make sure k_out's done flag (parity 1) reads done=1
    if (broke && b == 0 && tid == 0) {
        g_doneA[1] = 1;
        __threadfence();
    }
}

// ---------------- finalize + output ----------------
__global__ void k_out(float* __restrict__ out, int out_size) {
    int b = threadIdx.x;
    __shared__ float red[128];
    __shared__ int s_t[128];
    __shared__ int s_az;
    s_t[b] = g_targetA[(MSTEPS-1) & 1][b];
    __syncthreads();
    if (b == 0) { int a = 1; for (int i = 0; i < 128; i++) a &= (s_t[i] == 0); s_az = a; }
    __syncthreads();
    int done_prev = g_doneA[(MSTEPS-1) & 1];
    int done_t = (done_prev || s_az) ? 1 : 0;
    int tg = done_prev ? 0 : s_t[b];
    g_route[MSTEPS*B_ + b] = tg;
    if (!done_t) {
        g_flp[b] += g_logprob[b];
        g_len[b] += (tg != 0) ? 1.f : 0.f;
    }
    red[b] = g_flp[b] * g_len[b];
    __syncthreads();
    for (int s = 64; s > 0; s >>= 1) {
        if (b < s) red[b] += red[b + s];
        __syncthreads();
    }
    float loss = red[0] * (1.0f / 128.0f);
    __syncthreads();
    const int R = (MSTEPS+1)*B_;
    for (int i = b; i < out_size; i += 128) {
        float v;
        if (i < R)               v = (float)g_route[i];
        else if (i == R)         v = loss;
        else if (i < R + 1 + B_) v = g_flp[i - R - 1];
        else                     v = 0.f;
        out[i] = v;
    }
}

extern "C" void kernel_launch(void* const* d_in, const int* in_sizes, int n_in,
                              void* d_out, int out_size) {
    const float* hvec  = (const float*)d_in[0];
    const float* hbar  = (const float*)d_in[1];
    const int*   adj   = (const int*)  d_in[2];
    const int*   obj   = (const int*)  d_in[3];
    const int*   hml   = (const int*)  d_in[4];
    const float* qv_p  = (const float*)d_in[5];
    const float* kv_p  = (const float*)d_in[6];
    const float* vv_p  = (const float*)d_in[7];
    const float* ov_p  = (const float*)d_in[8];
    const float* qvf_W = (const float*)d_in[9];
    const float* qvf_b = (const float*)d_in[10];
    const float* kvf_W = (const float*)d_in[11];
    const float* kvf_b = (const float*)d_in[12];
    const float* vec_1 = (const float*)d_in[13];
    const float* vec_f = (const float*)d_in[14];
    float* out = (float*)d_out;

    k_init<<<1, 128>>>(obj, hml);
    k_tw<<<192, 256>>>(kvf_W, qvf_W, qv_p);
    k_gum<<<(MSTEPS*65536)/512, 512>>>();
    k_prep_kv<<<dim3(32, 128), 128>>>(hvec, kv_p, vv_p);
    k_prep_kvf<<<dim3(32, 128), 128>>>(hvec, kvf_b);

    k_steps<<<128, 1024>>>(hvec, hbar, adj, vec_1, vec_f, ov_p, qvf_b, obj, hml);

    k_out<<<1, 128>>>(out, out_size);
}

// round 16
// speedup vs baseline: 1.1187x; 1.1187x over previous
#include <cuda_runtime.h>
#include <math.h>

#define B_ 128
#define N_ 512
#define U_ 128
#define MSTEPS 70

// ---------------- device scratch ----------------
__device__ float g_kv [B_*128*N_];     // [b][h*16+d][n]
__device__ float g_vv [B_*128*N_];     // [b][h*16+d][n]
__device__ float g_kvf[B_*U_*N_];      // [b][u][n]
__device__ float g_gum[MSTEPS*65536];  // gumbel noise [t][b*512+n]
__device__ float g_WTkvf[U_*U_];
__device__ float g_WTqvf[U_*U_];
__device__ float g_qvpT[128*384];      // qv_p transposed: [h*16+d][x]
__device__ int   g_route[(MSTEPS+1)*B_];
__device__ float g_flp[B_];
__device__ float g_len[B_];
__device__ int   g_doneA[2];
__device__ unsigned g_matched[B_];
__device__ int   g_check[B_];
__device__ int   g_targetA[2][B_];
__device__ float g_logprob[B_];
__device__ unsigned g_keys[MSTEPS*2];

// ---------------- Threefry-2x32-20 (JAX partitionable) ----------------
__device__ __forceinline__ void tf2x32(unsigned k0, unsigned k1, unsigned &x0, unsigned &x1) {
    unsigned ks2 = k0 ^ k1 ^ 0x1BD11BDAu;
    x0 += k0; x1 += k1;
#define TFR(r) { x0 += x1; x1 = (x1<<(r)) | (x1>>(32-(r))); x1 ^= x0; }
    TFR(13) TFR(15) TFR(26) TFR(6)
    x0 += k1;  x1 += ks2 + 1u;
    TFR(17) TFR(29) TFR(16) TFR(24)
    x0 += ks2; x1 += k0 + 2u;
    TFR(13) TFR(15) TFR(26) TFR(6)
    x0 += k0;  x1 += k1 + 3u;
    TFR(17) TFR(29) TFR(16) TFR(24)
    x0 += k1;  x1 += ks2 + 4u;
    TFR(13) TFR(15) TFR(26) TFR(6)
    x0 += ks2; x1 += k0 + 5u;
#undef TFR
}

// ---------------- accurate f32 transcendentals ----------------
__device__ __forceinline__ float expf_acc(float x) {
    if (x < -87.0f) return 0.f;
    float k = rintf(x * 1.4426950408889634f);
    float r = fmaf(k, -0.693359375f, x);
    r = fmaf(k, 2.12194440e-4f, r);
    float z = r * r;
    float p = 1.9875691500e-4f;
    p = fmaf(p, r, 1.3981999507e-3f);
    p = fmaf(p, r, 8.3334519073e-3f);
    p = fmaf(p, r, 4.1665795894e-2f);
    p = fmaf(p, r, 1.6666665459e-1f);
    p = fmaf(p, r, 5.0000001201e-1f);
    float res = fmaf(z, p, r) + 1.0f;
    int ki = (int)k;
    return res * __int_as_float((ki + 127) << 23);
}

__device__ __forceinline__ float logf_acc(float x) {
    int hx = __float_as_int(x);
    int k = ((hx >> 23) & 0xff) - 127;
    hx = (hx & 0x7fffff) | 0x3f800000;
    float m = __int_as_float(hx);
    if (m >= 1.41421356237f) { m *= 0.5f; k++; }
    float f = m - 1.0f;
    float s = __fdiv_rn(f, 2.0f + f);
    float z = s * s;
    float w = z * z;
    float t1 = w * fmaf(w, 0.24279078841f, 0.40000972152f);
    float t2 = z * fmaf(w, 0.28498786688f, 0.66666662693f);
    float R = t2 + t1;
    float hfsq = 0.5f * f * f;
    float dk = (float)k;
    float r = fmaf(s, hfsq + R, dk * 9.0580006145e-06f);
    return dk * 0.69313812256f - ((hfsq - r) - f);
}

// ---------------- XLA fast-tanh ----------------
__device__ __forceinline__ float xla_tanhf(float x) {
    float ax = fabsf(x);
    const float cl = 7.90531110763549805f;
    float xc = fminf(fmaxf(x, -cl), cl);
    float x2 = xc * xc;
    float p = fmaf(x2, -2.76076847742355e-16f, 2.00018790482477e-13f);
    p = fmaf(x2, p, -8.60467152213735e-11f);
    p = fmaf(x2, p,  5.12229709037114e-08f);
    p = fmaf(x2, p,  1.48572235717979e-05f);
    p = fmaf(x2, p,  6.37261928875436e-04f);
    p = fmaf(x2, p,  4.89352455891786e-03f);
    p = p * xc;
    float q = fmaf(x2, 1.19825839466702e-06f, 1.18534705686654e-04f);
    q = fmaf(x2, q, 2.26843463243900e-03f);
    q = fmaf(x2, q, 4.89352518554385e-03f);
    float r = __fdiv_rn(p, q);
    return (ax < 0.0004f) ? x : r;
}

// ---------------- L2 policy loads ----------------
__device__ __forceinline__ unsigned long long pol_evict_last() {
    unsigned long long p;
    asm("createpolicy.fractional.L2::evict_last.b64 %0, 1.0;" : "=l"(p));
    return p;
}
__device__ __forceinline__ unsigned long long pol_evict_first() {
    unsigned long long p;
    asm("createpolicy.fractional.L2::evict_first.b64 %0, 1.0;" : "=l"(p));
    return p;
}
__device__ __forceinline__ float ldg_hint(const float* p, unsigned long long pol) {
    float v;
    asm("ld.global.nc.L2::cache_hint.f32 %0,[%1],%2;" : "=f"(v) : "l"(p), "l"(pol));
    return v;
}
__device__ __forceinline__ float4 ldg_hint4(const float4* p, unsigned long long pol) {
    float4 v;
    asm("ld.global.nc.L2::cache_hint.v4.f32 {%0,%1,%2,%3},[%4],%5;"
        : "=f"(v.x), "=f"(v.y), "=f"(v.z), "=f"(v.w) : "l"(p), "l"(pol));
    return v;
}

// ---------------- init ----------------
__global__ void k_init(const int* __restrict__ obj, const int* __restrict__ hml) {
    int b = threadIdx.x;
    for (int i = b; i < (MSTEPS+1)*B_; i += B_) g_route[i] = 0;
    g_flp[b] = 0.f; g_len[b] = 0.f;
    if (b == 0) { g_doneA[0] = 0; g_doneA[1] = 0; }
    if (b < MSTEPS) {
        unsigned x0 = 0u, x1 = (unsigned)b;
        tf2x32(0u, 42u, x0, x1);
        g_keys[2*b] = x0; g_keys[2*b+1] = x1;
    }
    int lz = 0;
    for (int m = 0; m < 16; m++) lz |= (hml[b*16 + m] == 0);
    int hz = __syncthreads_or(lz);
    unsigned mk = 0;
    for (int m = 0; m < 16; m++) {
        int v = hml[b*16 + m]; int mt = 0;
        for (int k = 0; k < 4; k++) mt |= (obj[k] == v);
        if (mt) mk |= (1u << m);
    }
    if (hz) mk |= 1u;
    g_matched[b] = mk;
    g_check[b] = (mk == 0xFFFFu) ? 1 : 0;
}

// ---------------- transposes (runs once) ----------------
__global__ void k_tw(const float* __restrict__ kvfW, const float* __restrict__ qvfW,
                     const float* __restrict__ qv_p) {
    int i = blockIdx.x * 256 + threadIdx.x;   // 49152 threads
    if (i < 16384) {
        int u = i >> 7, v = i & 127;
        g_WTkvf[v*128 + u] = kvfW[i];
        g_WTqvf[v*128 + u] = qvfW[i];
    }
    int r = i / 384, x = i % 384;
    g_qvpT[i] = qv_p[x*128 + r];
}

// ---------------- gumbel noise ----------------
__global__ void k_gum() {
    int idx = blockIdx.x * 512 + threadIdx.x;
    int t = idx >> 16, f = idx & 65535;
    unsigned x0 = 0u, x1 = (unsigned)f;
    tf2x32(g_keys[2*t], g_keys[2*t+1], x0, x1);
    unsigned bits = x0 ^ x1;
    float u0 = __uint_as_float((bits >> 9) | 0x3f800000u) - 1.0f;
    const float TINY = 1.17549435082228751e-38f;
    float uu = fmaxf(TINY, u0 + TINY);
    g_gum[idx] = -logf_acc(-logf_acc(uu));
}

// ---------------- precompute kv, vv (n-tile 16) ----------------
__global__ void k_prep_kv(const float* __restrict__ hvec, const float* __restrict__ kv_p,
                          const float* __restrict__ vv_p) {
    int b = blockIdx.y, n0 = blockIdx.x * 16;
    int t = threadIdx.x;
    __shared__ float hs[16*128];
    for (int i = t; i < 16*128; i += 128)
        hs[i] = hvec[(b*N_ + n0 + (i >> 7))*U_ + (i & 127)];
    __syncthreads();
    float ak[16], av[16];
#pragma unroll
    for (int j = 0; j < 16; j++) { ak[j] = 0.f; av[j] = 0.f; }
    for (int x = 0; x < 128; x++) {
        float kp = kv_p[x*128 + t];
        float vp = vv_p[x*128 + t];
#pragma unroll
        for (int j = 0; j < 16; j++) {
            float hx = hs[j*128 + x];
            ak[j] = fmaf(kp, hx, ak[j]);
            av[j] = fmaf(vp, hx, av[j]);
        }
    }
#pragma unroll
    for (int j = 0; j < 16; j++) {
        g_kv[(b*128 + t)*N_ + n0 + j] = ak[j];
        g_vv[(b*128 + t)*N_ + n0 + j] = av[j];
    }
}

// ---------------- precompute kvf (n-tile 16) ----------------
__global__ void k_prep_kvf(const float* __restrict__ hvec, const float* __restrict__ bias) {
    int b = blockIdx.y, n0 = blockIdx.x * 16;
    int u = threadIdx.x;
    __shared__ float hs[16*128];
    for (int i = u; i < 16*128; i += 128)
        hs[i] = hvec[(b*N_ + n0 + (i >> 7))*U_ + (i & 127)];
    __syncthreads();
    float a[16];
#pragma unroll
    for (int j = 0; j < 16; j++) a[j] = 0.f;
    for (int v = 0; v < 128; v++) {
        float w = g_WTkvf[v*128 + u];
#pragma unroll
        for (int j = 0; j < 16; j++) a[j] = fmaf(w, hs[j*128 + v], a[j]);
    }
    float bb = bias[u];
#pragma unroll
    for (int j = 0; j < 16; j++) g_kvf[(b*128 + u)*N_ + n0 + j] = a[j] + bb;
}

// ---------------- fused per-step kernel ----------------
__global__ void __launch_bounds__(1024, 1)
k_step(int t, const float* __restrict__ hvec, const float* __restrict__ hbar,
       const int* __restrict__ adj,
       const float* __restrict__ vec_1, const float* __restrict__ vec_f,
       const float* __restrict__ ov_p, const float* __restrict__ qvf_b,
       const int* __restrict__ obj, const int* __restrict__ hml) {
    int b = blockIdx.x;
    int tid = threadIdx.x;
    int half = tid >> 9;
    int hn   = tid & 511;
    int lane = tid & 31;
    int wid  = tid >> 5;
    int hwid = wid & 15;

    __shared__ float c_sh[384];
    __shared__ float qv_sh[128];
    __shared__ float w_sh[8][512];      // scores staging, then softmax weights
    __shared__ float s_redM[2][16][4];
    __shared__ float s_mx[8], s_sum[8];
    __shared__ float rec_sh[128];
    __shared__ float hc_sh[128];
    __shared__ float qvf_sh[128];
    __shared__ float logits_sh[512];
    __shared__ float s_v[16]; __shared__ int s_i[16];
    __shared__ float s_m[16], s_s[16];
    __shared__ float s_gmx;
    __shared__ int s_last, s_check, s_done;
    __shared__ int s_t[128];

    unsigned long long PEL = pol_evict_last();
    unsigned long long PEF = pol_evict_first();

    // ---- phase 0: apply previous step's sampled targets (stats) ----
    if (t == 0) {
        if (tid == 0) { s_last = 0; s_check = g_check[b]; s_done = 0; }
    } else {
        if (tid < 128) s_t[tid] = g_targetA[(t-1) & 1][tid];
        __syncthreads();
        if (tid == 0) {
            int done_prev = g_doneA[(t-1) & 1];
            int a = 1;
            for (int i = 0; i < 128; i++) a &= (s_t[i] == 0);
            int done_t = (done_prev || a) ? 1 : 0;
            int tg = done_prev ? 0 : s_t[b];
            g_route[t*B_ + b] = tg;
            if (!done_t) {
                g_flp[b] += g_logprob[b];
                g_len[b] += (tg != 0) ? 1.f : 0.f;
            }
            unsigned mk = g_matched[b];
#pragma unroll
            for (int m = 0; m < 16; m++) {
                int hv = hml[b*16 + m]; int mt = 0;
#pragma unroll
                for (int k2 = 0; k2 < 4; k2++) mt |= (obj[tg*4 + k2] == hv);
                if (mt) mk |= (1u << m);
            }
            g_matched[b] = mk;
            s_last = tg; s_check = (mk == 0xFFFFu) ? 1 : 0; s_done = done_t;
            if (b == 0) g_doneA[t & 1] = done_t;
        }
    }
    __syncthreads();
    if (s_done) return;

    // ---- context vector ----
    if (tid < 384) {
        float v;
        if (t == 0) {
            v = (tid < 128) ? hbar[tid]
              : (tid < 256) ? vec_1[b*U_ + tid - 128]
                            : vec_f[b*U_ + tid - 256];
        } else {
            int previ  = g_route[(t-1)*B_ + b];
            int firsti = (t == 1) ? s_last : g_route[B_ + b];
            v = (tid < 128) ? hbar[tid]
              : (tid < 256) ? hvec[(b*N_ + previ)*U_ + tid - 128]
                            : hvec[(b*N_ + firsti)*U_ + tid - 256];
        }
        c_sh[tid] = v;
    }
    __syncthreads();

    // ---- qv (coalesced transposed qv_p) ----
    {
        int d = hwid;
        for (int hh = 0; hh < 4; hh++) {
            int h = half*4 + hh;
            const float* qp = &g_qvpT[(h*16 + d)*384];
            float acc = 0.f;
            for (int x = lane; x < 384; x += 32)
                acc = fmaf(qp[x], c_sh[x], acc);
            for (int o = 16; o > 0; o >>= 1) acc += __shfl_down_sync(0xffffffffu, acc, o);
            if (lane == 0) qv_sh[h*16 + d] = acc;
        }
    }
    __syncthreads();

    // ---- scores: thread (h, ng) computes m for n=4ng..4ng+3 via float4,
    //      stages masked scores into w_sh (same values/order as before) ----
    {
        int h  = tid >> 7;          // 0..7
        int ng = tid & 127;         // 0..127
        const float4* kv4 = (const float4*)(&g_kv[(size_t)(b*128 + h*16)*N_]);
        float4 a; a.x = 0.f; a.y = 0.f; a.z = 0.f; a.w = 0.f;
#pragma unroll
        for (int d = 0; d < 16; d++) {
            float q = qv_sh[h*16 + d];
            float4 v = ldg_hint4(&kv4[d*128 + ng], PEF);
            a.x = fmaf(q, v.x, a.x); a.y = fmaf(q, v.y, a.y);
            a.z = fmaf(q, v.z, a.z); a.w = fmaf(q, v.w, a.w);
        }
        int4 av = *(const int4*)(&adj[s_last*N_ + 4*ng]);
        float aa[4] = {a.x, a.y, a.z, a.w};
        int   ad[4] = {av.x, av.y, av.z, av.w};
#pragma unroll
        for (int j = 0; j < 4; j++) {
            int n_ = 4*ng + j;
            bool aok = ad[j] != 0;
            bool dok = (n_ == 0) ? (s_check != 0) : (s_check == 0);
            w_sh[h][n_] = aok ? (dok ? aa[j]*0.25f : -1e10f) : -1e30f;
        }
    }
    __syncthreads();

    // ---- softmax: original (half, hn) mapping reads staged scores ----
    const int n = hn;
    float m4[4], e4[4];
#pragma unroll
    for (int hh = 0; hh < 4; hh++) m4[hh] = w_sh[half*4 + hh][n];
#pragma unroll
    for (int hh = 0; hh < 4; hh++) {
        float v = m4[hh];
        for (int o = 16; o > 0; o >>= 1) v = fmaxf(v, __shfl_down_sync(0xffffffffu, v, o));
        if (lane == 0) s_redM[half][hwid][hh] = v;
    }
    __syncthreads();
    if (tid < 8) {
        float x = s_redM[tid>>2][0][tid&3];
        for (int i = 1; i < 16; i++) x = fmaxf(x, s_redM[tid>>2][i][tid&3]);
        s_mx[tid] = x;
    }
    __syncthreads();
#pragma unroll
    for (int hh = 0; hh < 4; hh++) {
        float e = expf_acc(m4[hh] - s_mx[half*4 + hh]);
        e4[hh] = e;
        for (int o = 16; o > 0; o >>= 1) e += __shfl_down_sync(0xffffffffu, e, o);
        if (lane == 0) s_redM[half][hwid][hh] = e;
    }
    __syncthreads();
    if (tid < 8) {
        float x = 0.f;
        for (int i = 0; i < 16; i++) x += s_redM[tid>>2][i][tid&3];
        s_sum[tid] = x;
    }
    __syncthreads();
#pragma unroll
    for (int hh = 0; hh < 4; hh++)
        w_sh[half*4 + hh][n] = __fdiv_rn(e4[hh], s_sum[half*4 + hh]);
    __syncthreads();

    // ---- rec via warp-per-row (order-locked, unchanged) ----
    {
        int r0 = wid * 4;
#pragma unroll
        for (int rr = 0; rr < 4; rr++) {
            int r = r0 + rr;
            int h = r >> 4;
            const float* vvp = &g_vv[(b*128 + r)*N_];
            float acc = 0.f;
#pragma unroll
            for (int k = 0; k < 16; k++) {
                int nn = lane + k*32;
                acc = fmaf(w_sh[h][nn], ldg_hint(&vvp[nn], PEL), acc);
            }
            for (int o = 16; o > 0; o >>= 1) acc += __shfl_down_sync(0xffffffffu, acc, o);
            if (lane == 0) rec_sh[r] = acc;
        }
    }
    __syncthreads();

    // ---- FC ----
    if (tid < 128) {
        float a = 0.f;
        for (int i = 0; i < 128; i++) a = fmaf(ov_p[i*128 + tid], rec_sh[i], a);
        hc_sh[tid] = a;
    }
    __syncthreads();
    if (tid < 128) {
        float a = 0.f;
        for (int v = 0; v < 128; v++) a = fmaf(g_WTqvf[v*128 + tid], hc_sh[v], a);
        qvf_sh[tid] = a + qvf_b[tid];
    }
    __syncthreads();

    // ---- logits + gumbel sample ----
    float lg = 0.f;
    if (tid < 512) {
        float acc = 0.f;
        int base = b*128*N_ + n;
        for (int u = 0; u < 128; u++) acc = fmaf(qvf_sh[u], ldg_hint(&g_kvf[base + u*N_], PEL), acc);
        const float SQRTU = 11.3137084989847603904f;
        float cf = 10.0f * xla_tanhf(__fdiv_rn(acc, SQRTU));
        bool adj_ok = adj[s_last*N_ + n] != 0;
        bool dem_ok = (n == 0) ? (s_check != 0) : (s_check == 0);
        lg = adj_ok ? (dem_ok ? cf : -1e10f) : -1e30f;
        logits_sh[n] = lg;
        float g1 = ldg_hint(&g_gum[t*65536 + b*512 + n], PEF);
        float val = lg + g1;

        float bv = val; int bi = n;
#pragma unroll
        for (int o = 16; o > 0; o >>= 1) {
            float ov = __shfl_down_sync(0xffffffffu, bv, o);
            int   oi = __shfl_down_sync(0xffffffffu, bi, o);
            if (ov > bv || (ov == bv && oi < bi)) { bv = ov; bi = oi; }
        }
        float mv = lg;
        for (int o = 16; o > 0; o >>= 1) mv = fmaxf(mv, __shfl_down_sync(0xffffffffu, mv, o));
        if (lane == 0) { s_v[wid] = bv; s_i[wid] = bi; s_m[wid] = mv; }
    }
    __syncthreads();
    if (tid == 0) { float x = s_m[0]; for (int i = 1; i < 16; i++) x = fmaxf(x, s_m[i]); s_gmx = x; }
    __syncthreads();
    if (tid < 512) {
        float ee = expf_acc(lg - s_gmx);
        for (int o = 16; o > 0; o >>= 1) ee += __shfl_down_sync(0xffffffffu, ee, o);
        if (lane == 0) s_s[wid] = ee;
    }
    __syncthreads();
    if (tid == 0) {
        float bbv = s_v[0]; int bbi = s_i[0];
        for (int i = 1; i < 16; i++) {
            if (s_v[i] > bbv || (s_v[i] == bbv && s_i[i] < bbi)) { bbv = s_v[i]; bbi = s_i[i]; }
        }
        float sum = 0.f;
        for (int i = 0; i < 16; i++) sum += s_s[i];
        g_targetA[t & 1][b] = bbi;
        g_logprob[b] = (logits_sh[bbi] - s_gmx) - logf_acc(sum);
    }
}

// ---------------- finalize + output ----------------
__global__ void k_out(float* __restrict__ out, int out_size) {
    int b = threadIdx.x;
    __shared__ float red[128];
    __shared__ int s_t[128];
    __shared__ int s_az;
    s_t[b] = g_targetA[(MSTEPS-1) & 1][b];
    __syncthreads();
    if (b == 0) { int a = 1; for (int i = 0; i < 128; i++) a &= (s_t[i] == 0); s_az = a; }
    __syncthreads();
    int done_prev = g_doneA[(MSTEPS-1) & 1];
    int done_t = (done_prev || s_az) ? 1 : 0;
    int tg = done_prev ? 0 : s_t[b];
    g_route[MSTEPS*B_ + b] = tg;
    if (!done_t) {
        g_flp[b] += g_logprob[b];
        g_len[b] += (tg != 0) ? 1.f : 0.f;
    }
    red[b] = g_flp[b] * g_len[b];
    __syncthreads();
    for (int s = 64; s > 0; s >>= 1) {
        if (b < s) red[b] += red[b + s];
        __syncthreads();
    }
    float loss = red[0] * (1.0f / 128.0f);
    __syncthreads();
    const int R = (MSTEPS+1)*B_;
    for (int i = b; i < out_size; i += 128) {
        float v;
        if (i < R)               v = (float)g_route[i];
        else if (i == R)         v = loss;
        else if (i < R + 1 + B_) v = g_flp[i - R - 1];
        else                     v = 0.f;
        out[i] = v;
    }
}

extern "C" void kernel_launch(void* const* d_in, const int* in_sizes, int n_in,
                              void* d_out, int out_size) {
    const float* hvec  = (const float*)d_in[0];
    const float* hbar  = (const float*)d_in[1];
    const int*   adj   = (const int*)  d_in[2];
    const int*   obj   = (const int*)  d_in[3];
    const int*   hml   = (const int*)  d_in[4];
    const float* qv_p  = (const float*)d_in[5];
    const float* kv_p  = (const float*)d_in[6];
    const float* vv_p  = (const float*)d_in[7];
    const float* ov_p  = (const float*)d_in[8];
    const float* qvf_W = (const float*)d_in[9];
    const float* qvf_b = (const float*)d_in[10];
    const float* kvf_W = (const float*)d_in[11];
    const float* kvf_b = (const float*)d_in[12];
    const float* vec_1 = (const float*)d_in[13];
    const float* vec_f = (const float*)d_in[14];
    float* out = (float*)d_out;

    k_init<<<1, 128>>>(obj, hml);
    k_tw<<<192, 256>>>(kvf_W, qvf_W, qv_p);
    k_gum<<<(MSTEPS*65536)/512, 512>>>();
    k_prep_kv<<<dim3(32, 128), 128>>>(hvec, kv_p, vv_p);
    k_prep_kvf<<<dim3(32, 128), 128>>>(hvec, kvf_b);

    for (int t = 0; t < MSTEPS; t++) {
        k_step<<<128, 1024>>>(t, hvec, hbar, adj, vec_1, vec_f,
                              ov_p, qvf_b, obj, hml);
    }
    k_out<<<1, 128>>>(out, out_size);
}